// round 7
// baseline (speedup 1.0000x reference)
#include <cuda_runtime.h>
#include <cuda_fp16.h>
#include <stdint.h>

#define NN 8192
#define DH 64
#define KC 64              // j's per chunk
#define KSPLIT 2
#define KHALF (NN / KSPLIT)
#define NCH (KHALF / KC)   // 64 chunks
#define TPB 256
#define TILE_I 64
// smem: W tile 64x64 fp16 (8KB) x2, B tile 64x64 fp16 (8KB) x2
#define WOFF0 0
#define WOFF1 8192
#define BOFF0 16384
#define BOFF1 24576
#define SMEM_BYTES 32768

// ---------------- device scratch ----------------
__device__ unsigned g_adjp[NN * 256];          // packed adjacency bits (8MB)
__device__ unsigned short g_WhT[DH * NN];      // Wh^T fp16 [64][8192]
__device__ uint2 g_iAC[NN];                    // {half2(exp(src)), half2(exp(.2src))}
__device__ unsigned short g_jB[NN];            // half exp(dst)
__device__ unsigned short g_jD[NN];            // half exp(.2 dst)
__device__ float g_part[KSPLIT * NN * DH];     // K-split partial numerators
__device__ float g_den[KSPLIT * NN];           // K-split partial denominators

// ---------------- helpers ----------------
__device__ __forceinline__ uint32_t smem_u32(const void* p) {
    uint32_t a;
    asm("{ .reg .u64 t; cvta.to.shared.u64 t, %1; cvt.u32.u64 %0, t; }" : "=r"(a) : "l"(p));
    return a;
}
#define SWZ(off) ((off) ^ (((off) >> 3) & 0x70))

#define CPA16(d, s) asm volatile("cp.async.cg.shared.global [%0], [%1], 16;" :: "r"(d), "l"(s))
#define CPA_COMMIT() asm volatile("cp.async.commit_group;" ::: "memory")
#define CPA_WAIT0()  asm volatile("cp.async.wait_group 0;" ::: "memory")

__device__ __forceinline__ void ldsm_x4(uint32_t& r0, uint32_t& r1, uint32_t& r2, uint32_t& r3,
                                        uint32_t a) {
    asm volatile("ldmatrix.sync.aligned.m8n8.x4.shared.b16 {%0,%1,%2,%3}, [%4];"
                 : "=r"(r0), "=r"(r1), "=r"(r2), "=r"(r3) : "r"(a));
}
__device__ __forceinline__ void mma16816(float* d, const uint32_t* a, const uint32_t* b) {
    asm volatile("mma.sync.aligned.m16n8k16.row.col.f32.f16.f16.f32 "
                 "{%0,%1,%2,%3}, {%4,%5,%6,%7}, {%8,%9}, {%0,%1,%2,%3};"
                 : "+f"(d[0]), "+f"(d[1]), "+f"(d[2]), "+f"(d[3])
                 : "r"(a[0]), "r"(a[1]), "r"(a[2]), "r"(a[3]), "r"(b[0]), "r"(b[1]));
}

// ---------------- prep: Wh^T fp16 + exp factors (fused combine for layer 1) ----------------
__global__ void __launch_bounds__(256) prep_kernel(const float* __restrict__ xa,
                                                   const float* __restrict__ xb,
                                                   const float* __restrict__ Wm,
                                                   const float* __restrict__ bv,
                                                   const float* __restrict__ av, int use_gx) {
    __shared__ float Ws[DH * DH];
    __shared__ float as_[2 * DH];
    __shared__ float bs[DH];
    int t = threadIdx.x;
    for (int k = t; k < DH * DH; k += 256) Ws[k] = Wm[k];
    if (t < 2 * DH) as_[t] = av[t];
    if (t < DH) bs[t] = bv[t];
    __syncthreads();

    int row_loc = t >> 2, q = t & 3;
    int row = blockIdx.x * 64 + row_loc;

    float x[DH];
    if (use_gx) {
        const float* p0 = g_part + (size_t)row * DH;
        const float* p1 = g_part + (size_t)NN * DH + (size_t)row * DH;
        float inv = 1.0f / (g_den[row] + g_den[NN + row]);
#pragma unroll
        for (int j = 0; j < 16; j++) {
            float4 v0 = ((const float4*)p0)[j];
            float4 v1 = ((const float4*)p1)[j];
            x[4 * j]     = fmaxf((v0.x + v1.x) * inv, 0.f);
            x[4 * j + 1] = fmaxf((v0.y + v1.y) * inv, 0.f);
            x[4 * j + 2] = fmaxf((v0.z + v1.z) * inv, 0.f);
            x[4 * j + 3] = fmaxf((v0.w + v1.w) * inv, 0.f);
        }
    } else {
        const float* xr = row < NN / 2 ? xa + (size_t)row * DH
                                       : xb + (size_t)(row - NN / 2) * DH;
#pragma unroll
        for (int j = 0; j < 16; j++) {
            float4 v = ((const float4*)xr)[j];
            x[4 * j] = v.x; x[4 * j + 1] = v.y; x[4 * j + 2] = v.z; x[4 * j + 3] = v.w;
        }
    }

    float srcv = 0.f, dstv = 0.f;
#pragma unroll
    for (int ii = 0; ii < 16; ii++) {
        int i = q * 16 + ii;
        const float4* w4 = (const float4*)(Ws + i * DH);
        float a0 = 0.f, a1 = 0.f, a2 = 0.f, a3 = 0.f;
#pragma unroll
        for (int p = 0; p < 16; p += 4) {
            float4 w;
            w = w4[p];     a0 = fmaf(x[4*p+3], w.w, fmaf(x[4*p+2], w.z, fmaf(x[4*p+1], w.y, fmaf(x[4*p], w.x, a0))));
            w = w4[p + 1]; a1 = fmaf(x[4*p+7], w.w, fmaf(x[4*p+6], w.z, fmaf(x[4*p+5], w.y, fmaf(x[4*p+4], w.x, a1))));
            w = w4[p + 2]; a2 = fmaf(x[4*p+11], w.w, fmaf(x[4*p+10], w.z, fmaf(x[4*p+9], w.y, fmaf(x[4*p+8], w.x, a2))));
            w = w4[p + 3]; a3 = fmaf(x[4*p+15], w.w, fmaf(x[4*p+14], w.z, fmaf(x[4*p+13], w.y, fmaf(x[4*p+12], w.x, a3))));
        }
        float wh = bs[i] + ((a0 + a1) + (a2 + a3));
        srcv = fmaf(wh, as_[i], srcv);
        dstv = fmaf(wh, as_[DH + i], dstv);
        g_WhT[(size_t)i * NN + row] = __half_as_ushort(__float2half_rn(wh));
    }
    srcv += __shfl_xor_sync(0xffffffffu, srcv, 1);
    srcv += __shfl_xor_sync(0xffffffffu, srcv, 2);
    dstv += __shfl_xor_sync(0xffffffffu, dstv, 1);
    dstv += __shfl_xor_sync(0xffffffffu, dstv, 2);
    if (q == 0) {
        __half2 Ah = __float2half2_rn(expf(srcv));
        __half2 Ch = __float2half2_rn(expf(0.2f * srcv));
        g_iAC[row] = make_uint2(*(uint32_t*)&Ah, *(uint32_t*)&Ch);
        g_jB[row] = __half_as_ushort(__float2half_rn(expf(dstv)));
        g_jD[row] = __half_as_ushort(__float2half_rn(expf(0.2f * dstv)));
    }
}

// ---------------- gen one chunk: 32 j's per thread (half2) ----------------
// pBc/pDc point at this thread's 32 j-factors for this chunk.
template<int L0>
__device__ __forceinline__ void gen_chunk(char* smemp, uint32_t wo, const uint32_t* wdst,
                                          uint32_t A2, uint32_t C2,
                                          const uint4* pBc, const uint4* pDc,
                                          uint32_t bits, const int4* rv,
                                          unsigned* packdst, float& dsum) {
    __half2 A2h = *(__half2*)&A2, C2h = *(__half2*)&C2;
    uint32_t packbits = 0;
#pragma unroll
    for (int qq = 0; qq < 4; qq++) {
        uint4 Bq = pBc[qq], Dq = pDc[qq];
        uint32_t Bw[4] = {Bq.x, Bq.y, Bq.z, Bq.w};
        uint32_t Dw[4] = {Dq.x, Dq.y, Dq.z, Dq.w};
        uint32_t wv[4];
#pragma unroll
        for (int pp = 0; pp < 4; pp++) {
            int p = qq * 4 + pp;
            __half2 ab = __hmul2(A2h, *(__half2*)&Bw[pp]);
            __half2 cd = __hmul2(C2h, *(__half2*)&Dw[pp]);
            __half2 w = __hmax2(ab, cd);          // exp(leaky_relu(src+dst)) — exp monotone
            uint32_t m;
            if (L0) {
                int i = p >> 1;
                int v0 = (p & 1) ? rv[i].z : rv[i].x;
                int v1 = (p & 1) ? rv[i].w : rv[i].y;
                m = (v0 != 0 ? 0x0000FFFFu : 0u) | (v1 != 0 ? 0xFFFF0000u : 0u);
                packbits |= (v0 != 0 ? 1u : 0u) << (2 * p);
                packbits |= (v1 != 0 ? 1u : 0u) << (2 * p + 1);
            } else {
                uint32_t e = (bits >> (2 * p)) & 3u;
                uint32_t xm = (e * 0x8001u) & 0x10001u;
                m = xm * 0xFFFFu;
            }
            wv[pp] = (*(uint32_t*)&w) & m;
        }
        __half2 s01 = __hadd2(*(__half2*)&wv[0], *(__half2*)&wv[1]);
        __half2 s23 = __hadd2(*(__half2*)&wv[2], *(__half2*)&wv[3]);
        float2 fs = __half22float2(__hadd2(s01, s23));
        dsum += fs.x + fs.y;
        *(uint4*)(smemp + wo + wdst[qq]) = make_uint4(wv[0], wv[1], wv[2], wv[3]);
    }
    if (L0) *packdst = packbits;
}

// ---------------- attn: warp-specialized HMMA flash-GAT, 64x4096 per CTA ----------------
// warps 0-3: MMA consumers (32x32 warp tiles). warps 4-7: producers (gen + staging).
template<int L0>
__global__ void __launch_bounds__(TPB, 3) attn_mma(const int* __restrict__ adj) {
    extern __shared__ char smem[];
    uint32_t sb = smem_u32(smem);
    int t = threadIdx.x, wid = t >> 5, lane = t & 31;
    int tile = blockIdx.x >> 1, ks = blockIdx.x & 1;
    int i0 = tile * TILE_I, jbase = ks * KHALF;

    if (wid >= 4) {
        // ================= producer warps =================
        int g = t - 128;                 // 0..127
        int row_loc = g >> 1, jh = g & 1;
        int irow = i0 + row_loc;
        uint2 ac = g_iAC[irow];
        uint32_t wdst[4];
#pragma unroll
        for (int qq = 0; qq < 4; qq++)
            wdst[qq] = SWZ((uint32_t)(row_loc * 128 + jh * 64 + qq * 16));
        const uint4* pB = (const uint4*)(g_jB + jbase + jh * 32);   // +c*8
        const uint4* pD = (const uint4*)(g_jD + jbase + jh * 32);
        const int4* pAdj = (const int4*)(adj + (size_t)irow * NN + jbase) + jh * 8;  // +c*16
        unsigned* pPack = g_adjp + (size_t)irow * 256 + (jbase >> 5) + jh;           // +c*2
        float dsum = 0.f;

        // cp.async B-tile mapping: this thread stages row n=row_loc, k-offsets jh*4+r
        uint32_t bdst[4];
        const unsigned short* bsrc[4];
#pragma unroll
        for (int r = 0; r < 4; r++) {
            int ko = jh * 4 + r;
            bdst[r] = SWZ((uint32_t)(row_loc * 128 + ko * 16));
            bsrc[r] = g_WhT + (size_t)row_loc * NN + jbase + ko * 8;   // +c*64
        }

        // prefetch adj/bits chunk 0
        int4 rv[8];
        uint32_t bits = 0;
        if (L0) {
#pragma unroll
            for (int r = 0; r < 8; r++) rv[r] = pAdj[r];
        } else bits = pPack[0];

        // stage chunk 0
#pragma unroll
        for (int r = 0; r < 4; r++) CPA16(sb + BOFF0 + bdst[r], bsrc[r]);
        CPA_COMMIT();
        gen_chunk<L0>(smem, WOFF0, wdst, ac.x, ac.y, pB, pD, bits, rv, pPack, dsum);
        // prefetch adj chunk 1
        if (L0) {
#pragma unroll
            for (int r = 0; r < 8; r++) rv[r] = pAdj[16 + r];
        } else bits = pPack[2];
        CPA_WAIT0();
        __syncthreads();

        for (int c = 0; c < NCH; c++) {
            if (c + 1 < NCH) {
                int nb = (c + 1) & 1;
                uint32_t bo = nb ? BOFF1 : BOFF0, wo = nb ? WOFF1 : WOFF0;
#pragma unroll
                for (int r = 0; r < 4; r++) CPA16(sb + bo + bdst[r], bsrc[r] + (c + 1) * 64);
                CPA_COMMIT();
                gen_chunk<L0>(smem, wo, wdst, ac.x, ac.y,
                              pB + (size_t)(c + 1) * 8, pD + (size_t)(c + 1) * 8,
                              bits, rv, pPack + (c + 1) * 2, dsum);
                if (c + 2 < NCH) {
                    if (L0) {
#pragma unroll
                        for (int r = 0; r < 8; r++) rv[r] = pAdj[(c + 2) * 16 + r];
                    } else bits = pPack[(c + 2) * 2];
                }
                CPA_WAIT0();
            }
            __syncthreads();
        }

        // denominator: partner thread holds the other 32 j's of this row
        dsum += __shfl_xor_sync(0xffffffffu, dsum, 1);
        if (jh == 0) g_den[(size_t)ks * NN + irow] = dsum;
    } else {
        // ================= MMA warps: 32x32 tiles =================
        int wm2 = wid & 1, wn2 = wid >> 1;
        int lr = lane & 7, lsel = lane >> 3;
        float acc[2][4][4];
#pragma unroll
        for (int mt = 0; mt < 2; mt++)
#pragma unroll
            for (int nt = 0; nt < 4; nt++)
#pragma unroll
                for (int p = 0; p < 4; p++) acc[mt][nt][p] = 0.f;

        __syncthreads();   // matches producer preamble barrier

        for (int c = 0; c < NCH; c++) {
            int buf = c & 1;
            uint32_t wbase = sb + (buf ? WOFF1 : WOFF0);
            uint32_t bbase = sb + (buf ? BOFF1 : BOFF0);
#pragma unroll
            for (int k = 0; k < 4; k++) {
                uint32_t af[2][4], bf[8];
#pragma unroll
                for (int mt = 0; mt < 2; mt++) {
                    uint32_t a_adr = wbase + SWZ((uint32_t)((wm2 * 32 + mt * 16 + lr + (lsel & 1) * 8) * 128 + ((lsel >> 1) * 8 + k * 16) * 2));
                    ldsm_x4(af[mt][0], af[mt][1], af[mt][2], af[mt][3], a_adr);
                }
#pragma unroll
                for (int p = 0; p < 2; p++) {
                    uint32_t b_adr = bbase + SWZ((uint32_t)((wn2 * 32 + p * 16 + lr + (lsel >> 1) * 8) * 128 + ((lsel & 1) * 8 + k * 16) * 2));
                    ldsm_x4(bf[p * 4 + 0], bf[p * 4 + 1], bf[p * 4 + 2], bf[p * 4 + 3], b_adr);
                }
#pragma unroll
                for (int mt = 0; mt < 2; mt++) {
                    mma16816(acc[mt][0], af[mt], bf + 0);
                    mma16816(acc[mt][1], af[mt], bf + 2);
                    mma16816(acc[mt][2], af[mt], bf + 4);
                    mma16816(acc[mt][3], af[mt], bf + 6);
                }
            }
            __syncthreads();
        }

        // epilogue: write partial numerators
        float* base = g_part + (size_t)ks * NN * DH;
#pragma unroll
        for (int mt = 0; mt < 2; mt++) {
            int row0 = i0 + wm2 * 32 + mt * 16 + (lane >> 2);
#pragma unroll
            for (int nt = 0; nt < 4; nt++) {
                int col = wn2 * 32 + nt * 8 + (lane & 3) * 2;
                *(float2*)(base + (size_t)row0 * DH + col) = make_float2(acc[mt][nt][0], acc[mt][nt][1]);
                *(float2*)(base + (size_t)(row0 + 8) * DH + col) = make_float2(acc[mt][nt][2], acc[mt][nt][3]);
            }
        }
    }
}

// ---------------- final: fused combine + out = x @ out_w^T + out_b ----------------
__global__ void __launch_bounds__(256) final_kernel(const float* __restrict__ Wm,
                                                    const float* __restrict__ bv,
                                                    float* __restrict__ out) {
    __shared__ float Ws[DH * DH];
    __shared__ float bs[DH];
    int t = threadIdx.x;
    for (int k = t; k < DH * DH; k += 256) Ws[k] = Wm[k];
    if (t < DH) bs[t] = bv[t];
    __syncthreads();

    int row_loc = t >> 2, q = t & 3;
    int row = blockIdx.x * 64 + row_loc;

    const float* p0 = g_part + (size_t)row * DH;
    const float* p1 = g_part + (size_t)NN * DH + (size_t)row * DH;
    float inv = 1.0f / (g_den[row] + g_den[NN + row]);
    float x[DH];
#pragma unroll
    for (int j = 0; j < 16; j++) {
        float4 v0 = ((const float4*)p0)[j];
        float4 v1 = ((const float4*)p1)[j];
        x[4 * j]     = fmaxf((v0.x + v1.x) * inv, 0.f);
        x[4 * j + 1] = fmaxf((v0.y + v1.y) * inv, 0.f);
        x[4 * j + 2] = fmaxf((v0.z + v1.z) * inv, 0.f);
        x[4 * j + 3] = fmaxf((v0.w + v1.w) * inv, 0.f);
    }

    float res[16];
#pragma unroll
    for (int ii = 0; ii < 16; ii++) {
        int i = q * 16 + ii;
        const float4* w4 = (const float4*)(Ws + i * DH);
        float a0 = 0.f, a1 = 0.f, a2 = 0.f, a3 = 0.f;
#pragma unroll
        for (int p = 0; p < 16; p += 4) {
            float4 w;
            w = w4[p];     a0 = fmaf(x[4*p+3], w.w, fmaf(x[4*p+2], w.z, fmaf(x[4*p+1], w.y, fmaf(x[4*p], w.x, a0))));
            w = w4[p + 1]; a1 = fmaf(x[4*p+7], w.w, fmaf(x[4*p+6], w.z, fmaf(x[4*p+5], w.y, fmaf(x[4*p+4], w.x, a1))));
            w = w4[p + 2]; a2 = fmaf(x[4*p+11], w.w, fmaf(x[4*p+10], w.z, fmaf(x[4*p+9], w.y, fmaf(x[4*p+8], w.x, a2))));
            w = w4[p + 3]; a3 = fmaf(x[4*p+15], w.w, fmaf(x[4*p+14], w.z, fmaf(x[4*p+13], w.y, fmaf(x[4*p+12], w.x, a3))));
        }
        res[ii] = bs[i] + ((a0 + a1) + (a2 + a3));
    }
    float* orow = out + (size_t)row * DH + q * 16;
#pragma unroll
    for (int j = 0; j < 4; j++)
        ((float4*)orow)[j] = make_float4(res[4 * j], res[4 * j + 1], res[4 * j + 2], res[4 * j + 3]);
}

// ---------------- launch ----------------
extern "C" void kernel_launch(void* const* d_in, const int* in_sizes, int n_in,
                              void* d_out, int out_size) {
    const int*   adj  = (const int*)d_in[0];
    const float* user = (const float*)d_in[1];
    const float* item = (const float*)d_in[2];
    const float* W0   = (const float*)d_in[3];
    const float* b0   = (const float*)d_in[4];
    const float* a0   = (const float*)d_in[5];
    const float* W1   = (const float*)d_in[6];
    const float* b1   = (const float*)d_in[7];
    const float* a1   = (const float*)d_in[8];
    const float* ow   = (const float*)d_in[9];
    const float* ob   = (const float*)d_in[10];

    cudaFuncSetAttribute(attn_mma<1>, cudaFuncAttributeMaxDynamicSharedMemorySize, SMEM_BYTES);
    cudaFuncSetAttribute(attn_mma<0>, cudaFuncAttributeMaxDynamicSharedMemorySize, SMEM_BYTES);

    prep_kernel<<<NN / 64, 256>>>(user, item, W0, b0, a0, 0);
    attn_mma<1><<<(NN / TILE_I) * KSPLIT, TPB, SMEM_BYTES>>>(adj);   // fused: packs adj bits
    prep_kernel<<<NN / 64, 256>>>(nullptr, nullptr, W1, b1, a1, 1);  // fused combine
    attn_mma<0><<<(NN / TILE_I) * KSPLIT, TPB, SMEM_BYTES>>>(adj);   // reads packed bits
    final_kernel<<<NN / 64, 256>>>(ow, ob, (float*)d_out);           // fused combine
}

// round 8
// speedup vs baseline: 1.0990x; 1.0990x over previous
#include <cuda_runtime.h>
#include <cuda_fp16.h>
#include <stdint.h>

#define NN 8192
#define DH 64
#define KC 64               // j's per chunk
#define KSPLIT 4
#define KSEG (NN / KSPLIT)  // 2048
#define NCH (KSEG / KC)     // 32 chunks
#define TPB 256
#define TILE_I 64
// smem layout
#define WOFF0 0
#define WOFF1 8192
#define BOFF0 16384
#define BOFF1 24576
#define AOFF0 32768
#define AOFF1 (32768 + 17408)
#define ADJ_STRIDE 272      // 256B row + 16B pad (bank-conflict relief)
#define SMEM_BITS 32768
#define SMEM_L0   67584

// ---------------- device scratch ----------------
__device__ unsigned short g_adjp[NN * 512];    // packed adjacency bits (8MB)
__device__ unsigned short g_WhT[DH * NN];      // Wh^T fp16 [64][8192]
__device__ uint2 g_iAC[NN];                    // {half2(exp(src)), half2(exp(.2src))}
__device__ unsigned short g_jB[NN];            // half exp(dst)
__device__ unsigned short g_jD[NN];            // half exp(.2 dst)
__device__ float g_part[KSPLIT * NN * DH];     // K-split partial numerators
__device__ float g_den[KSPLIT * NN];           // K-split partial denominators

// ---------------- helpers ----------------
__device__ __forceinline__ uint32_t smem_u32(const void* p) {
    uint32_t a;
    asm("{ .reg .u64 t; cvta.to.shared.u64 t, %1; cvt.u32.u64 %0, t; }" : "=r"(a) : "l"(p));
    return a;
}
#define SWZ(off) ((off) ^ (((off) >> 3) & 0x70))

#define CPA16(d, s) asm volatile("cp.async.cg.shared.global [%0], [%1], 16;" :: "r"(d), "l"(s))
#define CPA_COMMIT() asm volatile("cp.async.commit_group;" ::: "memory")
#define CPA_WAIT0()  asm volatile("cp.async.wait_group 0;" ::: "memory")

__device__ __forceinline__ void ldsm_x4(uint32_t& r0, uint32_t& r1, uint32_t& r2, uint32_t& r3,
                                        uint32_t a) {
    asm volatile("ldmatrix.sync.aligned.m8n8.x4.shared.b16 {%0,%1,%2,%3}, [%4];"
                 : "=r"(r0), "=r"(r1), "=r"(r2), "=r"(r3) : "r"(a));
}
__device__ __forceinline__ void mma16816(float* d, const uint32_t* a, const uint32_t* b) {
    asm volatile("mma.sync.aligned.m16n8k16.row.col.f32.f16.f16.f32 "
                 "{%0,%1,%2,%3}, {%4,%5,%6,%7}, {%8,%9}, {%0,%1,%2,%3};"
                 : "+f"(d[0]), "+f"(d[1]), "+f"(d[2]), "+f"(d[3])
                 : "r"(a[0]), "r"(a[1]), "r"(a[2]), "r"(a[3]), "r"(b[0]), "r"(b[1]));
}

// ---------------- prep: Wh^T fp16 + exp factors (fused 4-way combine for layer 1) ---------
__global__ void __launch_bounds__(256) prep_kernel(const float* __restrict__ xa,
                                                   const float* __restrict__ xb,
                                                   const float* __restrict__ Wm,
                                                   const float* __restrict__ bv,
                                                   const float* __restrict__ av, int use_gx) {
    __shared__ float Ws[DH * DH];
    __shared__ float as_[2 * DH];
    __shared__ float bs[DH];
    int t = threadIdx.x;
    for (int k = t; k < DH * DH; k += 256) Ws[k] = Wm[k];
    if (t < 2 * DH) as_[t] = av[t];
    if (t < DH) bs[t] = bv[t];
    __syncthreads();

    int row_loc = t >> 2, q = t & 3;
    int row = blockIdx.x * 64 + row_loc;

    float x[DH];
    if (use_gx) {
        const float* p0 = g_part + (size_t)row * DH;
        const float* p1 = p0 + (size_t)NN * DH;
        const float* p2 = p1 + (size_t)NN * DH;
        const float* p3 = p2 + (size_t)NN * DH;
        float inv = 1.0f / (g_den[row] + g_den[NN + row] + g_den[2 * NN + row] + g_den[3 * NN + row]);
#pragma unroll
        for (int j = 0; j < 16; j++) {
            float4 v0 = ((const float4*)p0)[j];
            float4 v1 = ((const float4*)p1)[j];
            float4 v2 = ((const float4*)p2)[j];
            float4 v3 = ((const float4*)p3)[j];
            x[4 * j]     = fmaxf(((v0.x + v1.x) + (v2.x + v3.x)) * inv, 0.f);
            x[4 * j + 1] = fmaxf(((v0.y + v1.y) + (v2.y + v3.y)) * inv, 0.f);
            x[4 * j + 2] = fmaxf(((v0.z + v1.z) + (v2.z + v3.z)) * inv, 0.f);
            x[4 * j + 3] = fmaxf(((v0.w + v1.w) + (v2.w + v3.w)) * inv, 0.f);
        }
    } else {
        const float* xr = row < NN / 2 ? xa + (size_t)row * DH
                                       : xb + (size_t)(row - NN / 2) * DH;
#pragma unroll
        for (int j = 0; j < 16; j++) {
            float4 v = ((const float4*)xr)[j];
            x[4 * j] = v.x; x[4 * j + 1] = v.y; x[4 * j + 2] = v.z; x[4 * j + 3] = v.w;
        }
    }

    float srcv = 0.f, dstv = 0.f;
#pragma unroll
    for (int ii = 0; ii < 16; ii++) {
        int i = q * 16 + ii;
        const float4* w4 = (const float4*)(Ws + i * DH);
        float a0 = 0.f, a1 = 0.f, a2 = 0.f, a3 = 0.f;
#pragma unroll
        for (int p = 0; p < 16; p += 4) {
            float4 w;
            w = w4[p];     a0 = fmaf(x[4*p+3], w.w, fmaf(x[4*p+2], w.z, fmaf(x[4*p+1], w.y, fmaf(x[4*p], w.x, a0))));
            w = w4[p + 1]; a1 = fmaf(x[4*p+7], w.w, fmaf(x[4*p+6], w.z, fmaf(x[4*p+5], w.y, fmaf(x[4*p+4], w.x, a1))));
            w = w4[p + 2]; a2 = fmaf(x[4*p+11], w.w, fmaf(x[4*p+10], w.z, fmaf(x[4*p+9], w.y, fmaf(x[4*p+8], w.x, a2))));
            w = w4[p + 3]; a3 = fmaf(x[4*p+15], w.w, fmaf(x[4*p+14], w.z, fmaf(x[4*p+13], w.y, fmaf(x[4*p+12], w.x, a3))));
        }
        float wh = bs[i] + ((a0 + a1) + (a2 + a3));
        srcv = fmaf(wh, as_[i], srcv);
        dstv = fmaf(wh, as_[DH + i], dstv);
        g_WhT[(size_t)i * NN + row] = __half_as_ushort(__float2half_rn(wh));
    }
    srcv += __shfl_xor_sync(0xffffffffu, srcv, 1);
    srcv += __shfl_xor_sync(0xffffffffu, srcv, 2);
    dstv += __shfl_xor_sync(0xffffffffu, dstv, 1);
    dstv += __shfl_xor_sync(0xffffffffu, dstv, 2);
    if (q == 0) {
        __half2 Ah = __float2half2_rn(expf(srcv));
        __half2 Ch = __float2half2_rn(expf(0.2f * srcv));
        g_iAC[row] = make_uint2(*(uint32_t*)&Ah, *(uint32_t*)&Ch);
        g_jB[row] = __half_as_ushort(__float2half_rn(expf(dstv)));
        g_jD[row] = __half_as_ushort(__float2half_rn(expf(0.2f * dstv)));
    }
}

// ---------------- gen one chunk: 16 j's per thread (half2) ----------------
// L0: adjacency ints read from smem (adjsm); else packed bits (bits).
template<int L0>
__device__ __forceinline__ void gen_chunk(char* smemp, uint32_t wo,
                                          uint32_t wdst0, uint32_t wdst1,
                                          uint32_t A2, uint32_t C2,
                                          const uint4* pBc, const uint4* pDc,
                                          uint32_t bits, const int4* adjsm,
                                          unsigned short* packdst, float& dsum) {
    __half2 A2h = *(__half2*)&A2, C2h = *(__half2*)&C2;
    uint32_t packbits = 0;
    uint4 Bq0 = pBc[0], Bq1 = pBc[1], Dq0 = pDc[0], Dq1 = pDc[1];
    uint32_t Bw[8] = {Bq0.x, Bq0.y, Bq0.z, Bq0.w, Bq1.x, Bq1.y, Bq1.z, Bq1.w};
    uint32_t Dw[8] = {Dq0.x, Dq0.y, Dq0.z, Dq0.w, Dq1.x, Dq1.y, Dq1.z, Dq1.w};
    uint32_t wv[8];
#pragma unroll
    for (int p = 0; p < 8; p++) {
        __half2 ab = __hmul2(A2h, *(__half2*)&Bw[p]);
        __half2 cd = __hmul2(C2h, *(__half2*)&Dw[p]);
        __half2 w = __hmax2(ab, cd);      // exp(leaky_relu(src+dst)) — exp monotone
        uint32_t m;
        if (L0) {
            int4 a4 = adjsm[p >> 1];      // smem LDS.128, reused for p, p^1
            int v0 = (p & 1) ? a4.z : a4.x;
            int v1 = (p & 1) ? a4.w : a4.y;
            m = (v0 != 0 ? 0x0000FFFFu : 0u) | (v1 != 0 ? 0xFFFF0000u : 0u);
            packbits |= (v0 != 0 ? 1u : 0u) << (2 * p);
            packbits |= (v1 != 0 ? 1u : 0u) << (2 * p + 1);
        } else {
            uint32_t e = (bits >> (2 * p)) & 3u;
            uint32_t xm = (e * 0x8001u) & 0x10001u;
            m = xm * 0xFFFFu;
        }
        wv[p] = (*(uint32_t*)&w) & m;
    }
    __half2 s01 = __hadd2(*(__half2*)&wv[0], *(__half2*)&wv[1]);
    __half2 s23 = __hadd2(*(__half2*)&wv[2], *(__half2*)&wv[3]);
    __half2 s45 = __hadd2(*(__half2*)&wv[4], *(__half2*)&wv[5]);
    __half2 s67 = __hadd2(*(__half2*)&wv[6], *(__half2*)&wv[7]);
    float2 f0 = __half22float2(__hadd2(s01, s23));
    float2 f1 = __half22float2(__hadd2(s45, s67));
    dsum += (f0.x + f0.y) + (f1.x + f1.y);

    *(uint4*)(smemp + wo + wdst0) = make_uint4(wv[0], wv[1], wv[2], wv[3]);
    *(uint4*)(smemp + wo + wdst1) = make_uint4(wv[4], wv[5], wv[6], wv[7]);
    if (L0) *packdst = (unsigned short)packbits;
}

// ---------------- attn: homogeneous HMMA flash-GAT, 64 x 2048 per CTA ----------------
template<int L0, int MINB>
__global__ void __launch_bounds__(TPB, MINB) attn_mma(const int* __restrict__ adj) {
    extern __shared__ char smem[];
    uint32_t sb = smem_u32(smem);
    int t = threadIdx.x, wid = t >> 5, lane = t & 31;
    int tile = blockIdx.x >> 2, ks = blockIdx.x & 3;
    int i0 = tile * TILE_I, jbase = ks * KSEG;

    // ---- gen mapping: thread -> row i_loc, 16 j's at quarter jq16 ----
    int i_loc = t >> 2, jq16 = t & 3;
    int irow = i0 + i_loc;
    uint2 ac = g_iAC[irow];
    uint32_t wdst0 = SWZ((uint32_t)(i_loc * 128 + jq16 * 32));
    uint32_t wdst1 = SWZ((uint32_t)(i_loc * 128 + jq16 * 32 + 16));
    const uint4* pB = (const uint4*)(g_jB + jbase) + jq16 * 2;   // +c*8
    const uint4* pD = (const uint4*)(g_jD + jbase) + jq16 * 2;
    unsigned short* pPack = g_adjp + (size_t)irow * 512 + (jbase >> 4) + jq16;  // +c*4
    float dsum = 0.f;

    // ---- adj staging (L0): each thread stages/reads its own 64B ----
    const int* asrc = adj + (size_t)irow * NN + jbase + jq16 * 16;  // +c*64
    uint32_t adst = (uint32_t)(i_loc * ADJ_STRIDE + jq16 * 64);
    const int4* ard0 = (const int4*)(smem + AOFF0 + adst);
    const int4* ard1 = (const int4*)(smem + AOFF1 + adst);

    // ---- B staging (cp.async): 512 16B segs = 2/thread ----
    int s0 = t, s1 = t + 256;
    uint32_t bd0 = SWZ((uint32_t)((s0 >> 3) * 128 + (s0 & 7) * 16));
    uint32_t bd1 = SWZ((uint32_t)((s1 >> 3) * 128 + (s1 & 7) * 16));
    const unsigned short* bs0p = g_WhT + (size_t)(s0 >> 3) * NN + jbase + (s0 & 7) * 8;
    const unsigned short* bs1p = g_WhT + (size_t)(s1 >> 3) * NN + jbase + (s1 & 7) * 8;

    // ---- GEMM mapping: 8 warps = 4 M-tiles(16) x 2 N-halves(32) ----
    int wm = wid & 3, wn = wid >> 2;
    int lr = lane & 7, lsel = lane >> 3;
    float acc[4][4];
#pragma unroll
    for (int n = 0; n < 4; n++)
#pragma unroll
        for (int p = 0; p < 4; p++) acc[n][p] = 0.f;

    // ---- preamble ----
    uint32_t bits = 0;
    if (L0) {
        // stage adj(0) -> buf0
#pragma unroll
        for (int r = 0; r < 4; r++) CPA16(sb + AOFF0 + adst + r * 16, asrc + r * 4);
        CPA_COMMIT();
        CPA_WAIT0();
    } else {
        bits = pPack[0];
    }
    // stage B(0) (+ adj(1) for L0)
    CPA16(sb + BOFF0 + bd0, bs0p);
    CPA16(sb + BOFF0 + bd1, bs1p);
    if (L0) {
#pragma unroll
        for (int r = 0; r < 4; r++) CPA16(sb + AOFF1 + adst + r * 16, asrc + 64 + r * 4);
    }
    CPA_COMMIT();
    gen_chunk<L0>(smem, WOFF0, wdst0, wdst1, ac.x, ac.y, pB, pD, bits, ard0, pPack, dsum);
    if (!L0) bits = pPack[4];
    CPA_WAIT0();
    __syncthreads();

    for (int c = 0; c < NCH; c++) {
        int buf = c & 1;
        if (c + 1 < NCH) {
            int nb = buf ^ 1;
            uint32_t bo = nb ? BOFF1 : BOFF0, wo = nb ? WOFF1 : WOFF0;
            CPA16(sb + bo + bd0, bs0p + (c + 1) * 64);
            CPA16(sb + bo + bd1, bs1p + (c + 1) * 64);
            if (L0 && c + 2 < NCH) {
                uint32_t ao = buf ? AOFF1 : AOFF0;   // (c+2)&1 == buf
#pragma unroll
                for (int r = 0; r < 4; r++)
                    CPA16(sb + ao + adst + r * 16, asrc + (c + 2) * 64 + r * 4);
            }
            CPA_COMMIT();
            gen_chunk<L0>(smem, wo, wdst0, wdst1, ac.x, ac.y,
                          pB + (size_t)(c + 1) * 8, pD + (size_t)(c + 1) * 8,
                          bits, (buf ? ard0 : ard1) /* adj(c+1) in buf (c+1)&1 */,
                          pPack + (c + 1) * 4, dsum);
            if (!L0 && c + 2 < NCH) bits = pPack[(c + 2) * 4];
        }

        // ---- GEMM on chunk c ----
        uint32_t wbase = sb + (buf ? WOFF1 : WOFF0);
        uint32_t bbase = sb + (buf ? BOFF1 : BOFF0);
#pragma unroll
        for (int k = 0; k < 4; k++) {
            uint32_t af[4], bf[8];
            uint32_t a_adr = wbase + SWZ((uint32_t)((wm * 16 + lr + (lsel & 1) * 8) * 128 + ((lsel >> 1) * 8 + k * 16) * 2));
            ldsm_x4(af[0], af[1], af[2], af[3], a_adr);
#pragma unroll
            for (int p = 0; p < 2; p++) {
                uint32_t b_adr = bbase + SWZ((uint32_t)((wn * 32 + p * 16 + lr + (lsel >> 1) * 8) * 128 + ((lsel & 1) * 8 + k * 16) * 2));
                ldsm_x4(bf[p * 4 + 0], bf[p * 4 + 1], bf[p * 4 + 2], bf[p * 4 + 3], b_adr);
            }
            mma16816(acc[0], af, bf + 0);
            mma16816(acc[1], af, bf + 2);
            mma16816(acc[2], af, bf + 4);
            mma16816(acc[3], af, bf + 6);
        }
        CPA_WAIT0();
        __syncthreads();
    }

    // ---- denominator: reduce over the 4 gen threads of each row ----
    dsum += __shfl_xor_sync(0xffffffffu, dsum, 1);
    dsum += __shfl_xor_sync(0xffffffffu, dsum, 2);
    if (jq16 == 0) g_den[(size_t)ks * NN + irow] = dsum;

    // ---- epilogue: write partial numerators ----
    int row0 = i0 + wm * 16 + (lane >> 2);
    float* base = g_part + (size_t)ks * NN * DH;
#pragma unroll
    for (int nt = 0; nt < 4; nt++) {
        int col = wn * 32 + nt * 8 + (lane & 3) * 2;
        *(float2*)(base + (size_t)row0 * DH + col) = make_float2(acc[nt][0], acc[nt][1]);
        *(float2*)(base + (size_t)(row0 + 8) * DH + col) = make_float2(acc[nt][2], acc[nt][3]);
    }
}

// ---------------- final: fused 4-way combine + out = x @ out_w^T + out_b ----------------
__global__ void __launch_bounds__(256) final_kernel(const float* __restrict__ Wm,
                                                    const float* __restrict__ bv,
                                                    float* __restrict__ out) {
    __shared__ float Ws[DH * DH];
    __shared__ float bs[DH];
    int t = threadIdx.x;
    for (int k = t; k < DH * DH; k += 256) Ws[k] = Wm[k];
    if (t < DH) bs[t] = bv[t];
    __syncthreads();

    int row_loc = t >> 2, q = t & 3;
    int row = blockIdx.x * 64 + row_loc;

    const float* p0 = g_part + (size_t)row * DH;
    const float* p1 = p0 + (size_t)NN * DH;
    const float* p2 = p1 + (size_t)NN * DH;
    const float* p3 = p2 + (size_t)NN * DH;
    float inv = 1.0f / (g_den[row] + g_den[NN + row] + g_den[2 * NN + row] + g_den[3 * NN + row]);
    float x[DH];
#pragma unroll
    for (int j = 0; j < 16; j++) {
        float4 v0 = ((const float4*)p0)[j];
        float4 v1 = ((const float4*)p1)[j];
        float4 v2 = ((const float4*)p2)[j];
        float4 v3 = ((const float4*)p3)[j];
        x[4 * j]     = fmaxf(((v0.x + v1.x) + (v2.x + v3.x)) * inv, 0.f);
        x[4 * j + 1] = fmaxf(((v0.y + v1.y) + (v2.y + v3.y)) * inv, 0.f);
        x[4 * j + 2] = fmaxf(((v0.z + v1.z) + (v2.z + v3.z)) * inv, 0.f);
        x[4 * j + 3] = fmaxf(((v0.w + v1.w) + (v2.w + v3.w)) * inv, 0.f);
    }

    float res[16];
#pragma unroll
    for (int ii = 0; ii < 16; ii++) {
        int i = q * 16 + ii;
        const float4* w4 = (const float4*)(Ws + i * DH);
        float a0 = 0.f, a1 = 0.f, a2 = 0.f, a3 = 0.f;
#pragma unroll
        for (int p = 0; p < 16; p += 4) {
            float4 w;
            w = w4[p];     a0 = fmaf(x[4*p+3], w.w, fmaf(x[4*p+2], w.z, fmaf(x[4*p+1], w.y, fmaf(x[4*p], w.x, a0))));
            w = w4[p + 1]; a1 = fmaf(x[4*p+7], w.w, fmaf(x[4*p+6], w.z, fmaf(x[4*p+5], w.y, fmaf(x[4*p+4], w.x, a1))));
            w = w4[p + 2]; a2 = fmaf(x[4*p+11], w.w, fmaf(x[4*p+10], w.z, fmaf(x[4*p+9], w.y, fmaf(x[4*p+8], w.x, a2))));
            w = w4[p + 3]; a3 = fmaf(x[4*p+15], w.w, fmaf(x[4*p+14], w.z, fmaf(x[4*p+13], w.y, fmaf(x[4*p+12], w.x, a3))));
        }
        res[ii] = bs[i] + ((a0 + a1) + (a2 + a3));
    }
    float* orow = out + (size_t)row * DH + q * 16;
#pragma unroll
    for (int j = 0; j < 4; j++)
        ((float4*)orow)[j] = make_float4(res[4 * j], res[4 * j + 1], res[4 * j + 2], res[4 * j + 3]);
}

// ---------------- launch ----------------
extern "C" void kernel_launch(void* const* d_in, const int* in_sizes, int n_in,
                              void* d_out, int out_size) {
    const int*   adj  = (const int*)d_in[0];
    const float* user = (const float*)d_in[1];
    const float* item = (const float*)d_in[2];
    const float* W0   = (const float*)d_in[3];
    const float* b0   = (const float*)d_in[4];
    const float* a0   = (const float*)d_in[5];
    const float* W1   = (const float*)d_in[6];
    const float* b1   = (const float*)d_in[7];
    const float* a1   = (const float*)d_in[8];
    const float* ow   = (const float*)d_in[9];
    const float* ob   = (const float*)d_in[10];

    cudaFuncSetAttribute(attn_mma<1, 2>, cudaFuncAttributeMaxDynamicSharedMemorySize, SMEM_L0);
    cudaFuncSetAttribute(attn_mma<0, 3>, cudaFuncAttributeMaxDynamicSharedMemorySize, SMEM_BITS);

    prep_kernel<<<NN / 64, 256>>>(user, item, W0, b0, a0, 0);
    attn_mma<1, 2><<<(NN / TILE_I) * KSPLIT, TPB, SMEM_L0>>>(adj);    // raw adj via cp.async, packs bits
    prep_kernel<<<NN / 64, 256>>>(nullptr, nullptr, W1, b1, a1, 1);   // fused combine
    attn_mma<0, 3><<<(NN / TILE_I) * KSPLIT, TPB, SMEM_BITS>>>(adj);  // reads packed bits
    final_kernel<<<NN / 64, 256>>>(ow, ob, (float*)d_out);            // fused combine
}